// round 1
// baseline (speedup 1.0000x reference)
#include <cuda_runtime.h>
#include <math.h>

// ---------------- problem constants ----------------
constexpr int Bt  = 32;
constexpr int Dm  = 384;
constexpr int Hh  = 8;
constexpr int HD  = 48;
constexpr int NS  = 1024;          // 32*32 search tokens
constexpr int NT  = 256;           // 16*16 target tokens
constexpr int Ntok = NS + NT;      // 1280
constexpr int SKV = 256;           // 16*16 search kv tokens
constexpr int TKV = 64;            // 8*8 target kv tokens
constexpr int NKV = SKV + TKV;     // 320
constexpr int FF  = 4 * Dm;        // 1536
constexpr float EPS_LN = 1e-5f;
constexpr float EPS_BN = 1e-5f;
#define ATT_SCALE 0.14433756729740643f   // 1/sqrt(48)

// ---------------- scratch buffers (__device__ globals: allocation-free) ----------------
__device__ __align__(16) float g_xn  [Bt * Ntok * Dm];
__device__ __align__(16) float g_qact[Bt * Ntok * Dm];
__device__ __align__(16) float g_kact[Bt * NKV  * Dm];
__device__ __align__(16) float g_vact[Bt * NKV  * Dm];
__device__ __align__(16) float g_q   [Bt * Ntok * Dm];
__device__ __align__(16) float g_k   [Bt * NKV  * Dm];
__device__ __align__(16) float g_v   [Bt * NKV  * Dm];
__device__ __align__(16) float g_Ss  [(size_t)Bt * Hh * NS * NKV];  // search scores
__device__ __align__(16) float g_St  [(size_t)Bt * Hh * NT * TKV];  // target scores
__device__ __align__(16) float g_x1  [Bt * Ntok * Dm];
__device__ __align__(16) float g_h   [Bt * Ntok * Dm];
__device__ __align__(16) float g_hid [(size_t)Bt * Ntok * FF];

// ---------------- LayerNorm: one block per token, 128 threads x 3 elems ----------------
__global__ __launch_bounds__(128) void ln_kernel(const float* __restrict__ in,
                                                 const float* __restrict__ gamma,
                                                 const float* __restrict__ beta,
                                                 float* __restrict__ out) {
    __shared__ float red[8];
    __shared__ float s_mean, s_inv;
    size_t base = (size_t)blockIdx.x * Dm;
    int t = threadIdx.x;
    float v0 = in[base + t], v1 = in[base + t + 128], v2 = in[base + t + 256];
    float s  = v0 + v1 + v2;
    float ss = v0 * v0 + v1 * v1 + v2 * v2;
    #pragma unroll
    for (int o = 16; o > 0; o >>= 1) {
        s  += __shfl_xor_sync(0xffffffffu, s,  o);
        ss += __shfl_xor_sync(0xffffffffu, ss, o);
    }
    if ((t & 31) == 0) { red[t >> 5] = s; red[(t >> 5) + 4] = ss; }
    __syncthreads();
    if (t == 0) {
        float S  = red[0] + red[1] + red[2] + red[3];
        float SS = red[4] + red[5] + red[6] + red[7];
        float mean = S / (float)Dm;
        float var  = SS / (float)Dm - mean * mean;
        s_mean = mean;
        s_inv  = rsqrtf(var + EPS_LN);
    }
    __syncthreads();
    float mean = s_mean, inv = s_inv;
    out[base + t]       = (v0 - mean) * inv * gamma[t]       + beta[t];
    out[base + t + 128] = (v1 - mean) * inv * gamma[t + 128] + beta[t + 128];
    out[base + t + 256] = (v2 - mean) * inv * gamma[t + 256] + beta[t + 256];
}

// ---------------- depthwise 3x3 conv + BN affine ----------------
__global__ __launch_bounds__(256) void dwconv_kernel(const float* __restrict__ xn,
                                                     int in_off, int hw, int stride, int ohw,
                                                     const float* __restrict__ w,
                                                     const float* __restrict__ cb,
                                                     const float* __restrict__ bg,
                                                     const float* __restrict__ bb,
                                                     float* __restrict__ out,
                                                     int out_off, int out_ntok) {
    int idx = blockIdx.x * 256 + threadIdx.x;
    int total = Bt * ohw * ohw * Dm;
    if (idx >= total) return;
    int c = idx % Dm;
    int t = idx / Dm;
    int ox = t % ohw; t /= ohw;
    int oy = t % ohw;
    int b  = t / ohw;
    float acc = 0.f;
    const float* wc = w + c * 9;
    int iy0 = oy * stride - 1, ix0 = ox * stride - 1;
    #pragma unroll
    for (int dy = 0; dy < 3; dy++) {
        int iy = iy0 + dy;
        if ((unsigned)iy >= (unsigned)hw) continue;
        const float* rowp = xn + ((size_t)(b * Ntok + in_off + iy * hw)) * Dm + c;
        #pragma unroll
        for (int dx = 0; dx < 3; dx++) {
            int ix = ix0 + dx;
            if ((unsigned)ix < (unsigned)hw) acc += rowp[(size_t)ix * Dm] * wc[dy * 3 + dx];
        }
    }
    float y = acc + cb[c];
    y = y * (bg[c] * rsqrtf(1.0f + EPS_BN)) + bb[c];
    out[((size_t)(b * out_ntok + out_off + oy * ohw + ox)) * Dm + c] = y;
}

// ---------------- generic SGEMM: C[M,N] = A[M,K] * W[N,K]^T + bias, fused epilogues ---------
// epi: 0=none, 1=exact GELU, 2=residual add (res[M,N])
__global__ __launch_bounds__(256) void sgemm_kernel(const float* __restrict__ A,
                                                    const float* __restrict__ W,
                                                    const float* __restrict__ bias,
                                                    float* __restrict__ C,
                                                    int M, int N, int K, int epi,
                                                    const float* __restrict__ res) {
    __shared__ __align__(16) float As[16][128];
    __shared__ __align__(16) float Bs[16][128];
    const int bm = blockIdx.y * 128, bn = blockIdx.x * 128;
    int tid = threadIdx.x;
    int tx = tid & 15, ty = tid >> 4;
    float acc[8][8];
    #pragma unroll
    for (int i = 0; i < 8; i++)
        #pragma unroll
        for (int j = 0; j < 8; j++) acc[i][j] = 0.f;

    int lrow = tid >> 1;
    int lcol = (tid & 1) * 8;
    const float* Ap = A + (size_t)(bm + lrow) * K + lcol;
    const float* Wp = W + (size_t)(bn + lrow) * K + lcol;

    for (int kt = 0; kt < K; kt += 16) {
        float4 a0 = *(const float4*)(Ap + kt);
        float4 a1 = *(const float4*)(Ap + kt + 4);
        float4 w0 = *(const float4*)(Wp + kt);
        float4 w1 = *(const float4*)(Wp + kt + 4);
        As[lcol + 0][lrow] = a0.x; As[lcol + 1][lrow] = a0.y;
        As[lcol + 2][lrow] = a0.z; As[lcol + 3][lrow] = a0.w;
        As[lcol + 4][lrow] = a1.x; As[lcol + 5][lrow] = a1.y;
        As[lcol + 6][lrow] = a1.z; As[lcol + 7][lrow] = a1.w;
        Bs[lcol + 0][lrow] = w0.x; Bs[lcol + 1][lrow] = w0.y;
        Bs[lcol + 2][lrow] = w0.z; Bs[lcol + 3][lrow] = w0.w;
        Bs[lcol + 4][lrow] = w1.x; Bs[lcol + 5][lrow] = w1.y;
        Bs[lcol + 6][lrow] = w1.z; Bs[lcol + 7][lrow] = w1.w;
        __syncthreads();
        #pragma unroll
        for (int kk = 0; kk < 16; kk++) {
            float4 a0v = ((const float4*)As[kk])[ty * 2];
            float4 a1v = ((const float4*)As[kk])[ty * 2 + 1];
            float4 b0v = ((const float4*)Bs[kk])[tx * 2];
            float4 b1v = ((const float4*)Bs[kk])[tx * 2 + 1];
            float ar[8] = {a0v.x, a0v.y, a0v.z, a0v.w, a1v.x, a1v.y, a1v.z, a1v.w};
            float br[8] = {b0v.x, b0v.y, b0v.z, b0v.w, b1v.x, b1v.y, b1v.z, b1v.w};
            #pragma unroll
            for (int i = 0; i < 8; i++)
                #pragma unroll
                for (int j = 0; j < 8; j++) acc[i][j] += ar[i] * br[j];
        }
        __syncthreads();
    }

    #pragma unroll
    for (int i = 0; i < 8; i++) {
        int row = bm + ty * 8 + i;
        #pragma unroll
        for (int jj = 0; jj < 8; jj += 4) {
            int col = bn + tx * 8 + jj;
            float4 bv = *(const float4*)(bias + col);
            float4 v;
            v.x = acc[i][jj + 0] + bv.x;
            v.y = acc[i][jj + 1] + bv.y;
            v.z = acc[i][jj + 2] + bv.z;
            v.w = acc[i][jj + 3] + bv.w;
            if (epi == 1) {
                v.x = 0.5f * v.x * (1.0f + erff(v.x * 0.70710678118654752f));
                v.y = 0.5f * v.y * (1.0f + erff(v.y * 0.70710678118654752f));
                v.z = 0.5f * v.z * (1.0f + erff(v.z * 0.70710678118654752f));
                v.w = 0.5f * v.w * (1.0f + erff(v.w * 0.70710678118654752f));
            } else if (epi == 2) {
                float4 r = *(const float4*)(res + (size_t)row * N + col);
                v.x += r.x; v.y += r.y; v.z += r.z; v.w += r.w;
            }
            *(float4*)(C + (size_t)row * N + col) = v;
        }
    }
}

// ---------------- attention scores: S[bh,m,n] = scale * q . k ----------------
// grid: (Nk/64, Mq/32, B*H), 128 threads
__global__ __launch_bounds__(128) void score_kernel(const float* __restrict__ q,
                                                    const float* __restrict__ k,
                                                    float* __restrict__ S,
                                                    int Mq, int Nk, int q_off, int k_off) {
    __shared__ __align__(16) float Qs[HD][32];
    __shared__ __align__(16) float Ks[HD][64];
    int bh = blockIdx.z;
    int b = bh >> 3, h = bh & 7;
    int m0 = blockIdx.y * 32, n0 = blockIdx.x * 64;
    int tid = threadIdx.x;

    for (int idx = tid; idx < HD * 32; idx += 128) {
        int d = idx >> 5, r = idx & 31;
        Qs[d][r] = q[((size_t)(b * Ntok + q_off + m0 + r)) * Dm + h * HD + d];
    }
    for (int idx = tid; idx < HD * 64; idx += 128) {
        int d = idx >> 6, r = idx & 63;
        Ks[d][r] = k[((size_t)(b * NKV + k_off + n0 + r)) * Dm + h * HD + d];
    }
    __syncthreads();

    int tn = tid & 15, tm = tid >> 4;
    float acc[4][4];
    #pragma unroll
    for (int i = 0; i < 4; i++)
        #pragma unroll
        for (int j = 0; j < 4; j++) acc[i][j] = 0.f;

    #pragma unroll
    for (int d = 0; d < HD; d++) {
        float4 av = ((const float4*)Qs[d])[tm];
        float4 bv = ((const float4*)Ks[d])[tn];
        float ar[4] = {av.x, av.y, av.z, av.w};
        float br[4] = {bv.x, bv.y, bv.z, bv.w};
        #pragma unroll
        for (int i = 0; i < 4; i++)
            #pragma unroll
            for (int j = 0; j < 4; j++) acc[i][j] += ar[i] * br[j];
    }

    float* Sp = S + (size_t)bh * Mq * Nk;
    #pragma unroll
    for (int i = 0; i < 4; i++) {
        float4 v;
        v.x = acc[i][0] * ATT_SCALE; v.y = acc[i][1] * ATT_SCALE;
        v.z = acc[i][2] * ATT_SCALE; v.w = acc[i][3] * ATT_SCALE;
        *(float4*)(Sp + (size_t)(m0 + tm * 4 + i) * Nk + n0 + tn * 4) = v;
    }
}

// ---------------- row softmax (in place), one block per row ----------------
__global__ __launch_bounds__(128) void softmax_kernel(float* __restrict__ S, int len) {
    float* row = S + (size_t)blockIdx.x * len;
    int t = threadIdx.x;
    __shared__ float red[4];
    __shared__ float s_bc;
    float m = -3.4e38f;
    for (int i = t; i < len; i += 128) m = fmaxf(m, row[i]);
    #pragma unroll
    for (int o = 16; o > 0; o >>= 1) m = fmaxf(m, __shfl_xor_sync(0xffffffffu, m, o));
    if ((t & 31) == 0) red[t >> 5] = m;
    __syncthreads();
    if (t == 0) s_bc = fmaxf(fmaxf(red[0], red[1]), fmaxf(red[2], red[3]));
    __syncthreads();
    float rowmax = s_bc;
    float sum = 0.f;
    for (int i = t; i < len; i += 128) {
        float e = __expf(row[i] - rowmax);
        row[i] = e;
        sum += e;
    }
    #pragma unroll
    for (int o = 16; o > 0; o >>= 1) sum += __shfl_xor_sync(0xffffffffu, sum, o);
    __syncthreads();                       // everyone has read s_bc
    if ((t & 31) == 0) red[t >> 5] = sum;
    __syncthreads();
    if (t == 0) s_bc = red[0] + red[1] + red[2] + red[3];
    __syncthreads();
    float inv = 1.0f / s_bc;
    for (int i = t; i < len; i += 128) row[i] *= inv;
}

// ---------------- PV: x1 = x + P @ V   (1 thread = 1 query row, 48-reg acc) -------------
// grid: (Mq/128, B*H), 128 threads
__global__ __launch_bounds__(128) void pv_kernel(const float* __restrict__ P,
                                                 const float* __restrict__ v,
                                                 const float* __restrict__ x,
                                                 float* __restrict__ x1,
                                                 int Mq, int Nk, int q_off, int k_off) {
    __shared__ __align__(16) float Ps[128][65];
    __shared__ __align__(16) float Vs[64][52];
    int bh = blockIdx.y;
    int b = bh >> 3, h = bh & 7;
    int m0 = blockIdx.x * 128;
    int tid = threadIdx.x;
    float acc[48];
    #pragma unroll
    for (int j = 0; j < 48; j++) acc[j] = 0.f;

    const float* Prow = P + ((size_t)bh * Mq + m0) * Nk;
    for (int n0 = 0; n0 < Nk; n0 += 64) {
        for (int idx = tid; idx < 128 * 64; idx += 128) {
            int r = idx >> 6, c = idx & 63;
            Ps[r][c] = Prow[(size_t)r * Nk + n0 + c];
        }
        for (int idx = tid; idx < 64 * 48; idx += 128) {
            int r = idx / 48, c = idx % 48;
            Vs[r][c] = v[((size_t)(b * NKV + k_off + n0 + r)) * Dm + h * HD + c];
        }
        __syncthreads();
        #pragma unroll 4
        for (int n = 0; n < 64; n++) {
            float p = Ps[tid][n];
            const float4* vr = (const float4*)Vs[n];
            #pragma unroll
            for (int j = 0; j < 12; j++) {
                float4 vv = vr[j];
                acc[j * 4 + 0] += p * vv.x;
                acc[j * 4 + 1] += p * vv.y;
                acc[j * 4 + 2] += p * vv.z;
                acc[j * 4 + 3] += p * vv.w;
            }
        }
        __syncthreads();
    }
    size_t base = ((size_t)(b * Ntok + q_off + m0 + tid)) * Dm + h * HD;
    #pragma unroll
    for (int j = 0; j < 12; j++) {
        float4 xv = *(const float4*)(x + base + j * 4);
        float4 o;
        o.x = xv.x + acc[j * 4 + 0];
        o.y = xv.y + acc[j * 4 + 1];
        o.z = xv.z + acc[j * 4 + 2];
        o.w = xv.w + acc[j * 4 + 3];
        *(float4*)(x1 + base + j * 4) = o;
    }
}

// ---------------- launch ----------------
extern "C" void kernel_launch(void* const* d_in, const int* in_sizes, int n_in,
                              void* d_out, int out_size) {
    const float* x      = (const float*)d_in[0];
    const float* ln1_g  = (const float*)d_in[1];
    const float* ln1_b  = (const float*)d_in[2];
    const float* dwq_w  = (const float*)d_in[3];
    const float* dwq_b  = (const float*)d_in[4];
    const float* bnq_g  = (const float*)d_in[5];
    const float* bnq_b  = (const float*)d_in[6];
    const float* dwk_w  = (const float*)d_in[7];
    const float* dwk_b  = (const float*)d_in[8];
    const float* bnk_g  = (const float*)d_in[9];
    const float* bnk_b  = (const float*)d_in[10];
    const float* dwv_w  = (const float*)d_in[11];
    const float* dwv_b  = (const float*)d_in[12];
    const float* bnv_g  = (const float*)d_in[13];
    const float* bnv_b  = (const float*)d_in[14];
    const float* pq_w   = (const float*)d_in[15];
    const float* pq_b   = (const float*)d_in[16];
    const float* pk_w   = (const float*)d_in[17];
    const float* pk_b   = (const float*)d_in[18];
    const float* pv_w   = (const float*)d_in[19];
    const float* pv_b   = (const float*)d_in[20];
    const float* ln2_g  = (const float*)d_in[21];
    const float* ln2_b  = (const float*)d_in[22];
    const float* ff1_w  = (const float*)d_in[23];
    const float* ff1_b  = (const float*)d_in[24];
    const float* ff2_w  = (const float*)d_in[25];
    const float* ff2_b  = (const float*)d_in[26];
    float* out = (float*)d_out;

    float *xn, *qact, *kact, *vact, *q, *k, *v, *Ss, *St, *x1, *h, *hid;
    cudaGetSymbolAddress((void**)&xn,   g_xn);
    cudaGetSymbolAddress((void**)&qact, g_qact);
    cudaGetSymbolAddress((void**)&kact, g_kact);
    cudaGetSymbolAddress((void**)&vact, g_vact);
    cudaGetSymbolAddress((void**)&q,    g_q);
    cudaGetSymbolAddress((void**)&k,    g_k);
    cudaGetSymbolAddress((void**)&v,    g_v);
    cudaGetSymbolAddress((void**)&Ss,   g_Ss);
    cudaGetSymbolAddress((void**)&St,   g_St);
    cudaGetSymbolAddress((void**)&x1,   g_x1);
    cudaGetSymbolAddress((void**)&h,    g_h);
    cudaGetSymbolAddress((void**)&hid,  g_hid);

    // 1) LN1
    ln_kernel<<<Bt * Ntok, 128>>>(x, ln1_g, ln1_b, xn);

    // 2) depthwise convs + BN (q: stride 1, k/v: stride 2)
    {
        int tot;
        tot = Bt * 32 * 32 * Dm;
        dwconv_kernel<<<(tot + 255) / 256, 256>>>(xn, 0,  32, 1, 32, dwq_w, dwq_b, bnq_g, bnq_b, qact, 0,  Ntok);
        tot = Bt * 16 * 16 * Dm;
        dwconv_kernel<<<(tot + 255) / 256, 256>>>(xn, NS, 16, 1, 16, dwq_w, dwq_b, bnq_g, bnq_b, qact, NS, Ntok);
        tot = Bt * 16 * 16 * Dm;
        dwconv_kernel<<<(tot + 255) / 256, 256>>>(xn, 0,  32, 2, 16, dwk_w, dwk_b, bnk_g, bnk_b, kact, 0,  NKV);
        tot = Bt * 8 * 8 * Dm;
        dwconv_kernel<<<(tot + 255) / 256, 256>>>(xn, NS, 16, 2, 8,  dwk_w, dwk_b, bnk_g, bnk_b, kact, SKV, NKV);
        tot = Bt * 16 * 16 * Dm;
        dwconv_kernel<<<(tot + 255) / 256, 256>>>(xn, 0,  32, 2, 16, dwv_w, dwv_b, bnv_g, bnv_b, vact, 0,  NKV);
        tot = Bt * 8 * 8 * Dm;
        dwconv_kernel<<<(tot + 255) / 256, 256>>>(xn, NS, 16, 2, 8,  dwv_w, dwv_b, bnv_g, bnv_b, vact, SKV, NKV);
    }

    // 3) q/k/v projections
    {
        dim3 gq(Dm / 128, (Bt * Ntok) / 128);
        sgemm_kernel<<<gq, 256>>>(qact, pq_w, pq_b, q, Bt * Ntok, Dm, Dm, 0, nullptr);
        dim3 gk(Dm / 128, (Bt * NKV) / 128);
        sgemm_kernel<<<gk, 256>>>(kact, pk_w, pk_b, k, Bt * NKV, Dm, Dm, 0, nullptr);
        sgemm_kernel<<<gk, 256>>>(vact, pv_w, pv_b, v, Bt * NKV, Dm, Dm, 0, nullptr);
    }

    // 4) attention: scores -> softmax -> PV (+ residual with x)
    score_kernel<<<dim3(NKV / 64, NS / 32, Bt * Hh), 128>>>(q, k, Ss, NS, NKV, 0, 0);
    score_kernel<<<dim3(TKV / 64, NT / 32, Bt * Hh), 128>>>(q, k, St, NT, TKV, NS, SKV);
    softmax_kernel<<<Bt * Hh * NS, 128>>>(Ss, NKV);
    softmax_kernel<<<Bt * Hh * NT, 128>>>(St, TKV);
    pv_kernel<<<dim3(NS / 128, Bt * Hh), 128>>>(Ss, v, x, x1, NS, NKV, 0, 0);
    pv_kernel<<<dim3(NT / 128, Bt * Hh), 128>>>(St, v, x, x1, NT, TKV, NS, SKV);

    // 5) LN2 + FFN (GELU fused into FF1 epilogue, residual fused into FF2 epilogue)
    ln_kernel<<<Bt * Ntok, 128>>>(x1, ln2_g, ln2_b, h);
    {
        dim3 g1(FF / 128, (Bt * Ntok) / 128);
        sgemm_kernel<<<g1, 256>>>(h, ff1_w, ff1_b, hid, Bt * Ntok, FF, Dm, 1, nullptr);
        dim3 g2(Dm / 128, (Bt * Ntok) / 128);
        sgemm_kernel<<<g2, 256>>>(hid, ff2_w, ff2_b, out, Bt * Ntok, Dm, FF, 2, x1);
    }
}

// round 2
// speedup vs baseline: 1.4731x; 1.4731x over previous
#include <cuda_runtime.h>
#include <math.h>
#include <stdint.h>

// ---------------- problem constants ----------------
constexpr int Bt  = 32;
constexpr int Dm  = 384;
constexpr int Hh  = 8;
constexpr int HD  = 48;
constexpr int NS  = 1024;          // 32*32 search tokens
constexpr int NT  = 256;           // 16*16 target tokens
constexpr int Ntok = NS + NT;      // 1280
constexpr int SKV = 256;           // 16*16 search kv tokens
constexpr int TKV = 64;            // 8*8 target kv tokens
constexpr int NKV = SKV + TKV;     // 320
constexpr int FF  = 4 * Dm;        // 1536
constexpr float EPS_LN = 1e-5f;
constexpr float EPS_BN = 1e-5f;
#define ATT_SCALE 0.14433756729740643f   // 1/sqrt(48)

// ---------------- scratch buffers ----------------
__device__ __align__(16) float g_xn  [Bt * Ntok * Dm];
__device__ __align__(16) float g_qact[Bt * Ntok * Dm];
__device__ __align__(16) float g_kact[Bt * NKV  * Dm];
__device__ __align__(16) float g_vact[Bt * NKV  * Dm];
__device__ __align__(16) float g_q   [Bt * Ntok * Dm];
__device__ __align__(16) float g_k   [Bt * NKV  * Dm];
__device__ __align__(16) float g_v   [Bt * NKV  * Dm];
__device__ __align__(16) float g_Ss  [(size_t)Bt * Hh * NS * NKV];
__device__ __align__(16) float g_St  [(size_t)Bt * Hh * NT * TKV];
__device__ __align__(16) float g_x1  [Bt * Ntok * Dm];
__device__ __align__(16) float g_h   [Bt * Ntok * Dm];
__device__ __align__(16) float g_hid [(size_t)Bt * Ntok * FF];

// ---------------- LayerNorm ----------------
__global__ __launch_bounds__(128) void ln_kernel(const float* __restrict__ in,
                                                 const float* __restrict__ gamma,
                                                 const float* __restrict__ beta,
                                                 float* __restrict__ out) {
    __shared__ float red[8];
    __shared__ float s_mean, s_inv;
    size_t base = (size_t)blockIdx.x * Dm;
    int t = threadIdx.x;
    float v0 = in[base + t], v1 = in[base + t + 128], v2 = in[base + t + 256];
    float s  = v0 + v1 + v2;
    float ss = v0 * v0 + v1 * v1 + v2 * v2;
    #pragma unroll
    for (int o = 16; o > 0; o >>= 1) {
        s  += __shfl_xor_sync(0xffffffffu, s,  o);
        ss += __shfl_xor_sync(0xffffffffu, ss, o);
    }
    if ((t & 31) == 0) { red[t >> 5] = s; red[(t >> 5) + 4] = ss; }
    __syncthreads();
    if (t == 0) {
        float S  = red[0] + red[1] + red[2] + red[3];
        float SS = red[4] + red[5] + red[6] + red[7];
        float mean = S / (float)Dm;
        float var  = SS / (float)Dm - mean * mean;
        s_mean = mean;
        s_inv  = rsqrtf(var + EPS_LN);
    }
    __syncthreads();
    float mean = s_mean, inv = s_inv;
    out[base + t]       = (v0 - mean) * inv * gamma[t]       + beta[t];
    out[base + t + 128] = (v1 - mean) * inv * gamma[t + 128] + beta[t + 128];
    out[base + t + 256] = (v2 - mean) * inv * gamma[t + 256] + beta[t + 256];
}

// ---------------- depthwise 3x3 conv + BN affine ----------------
__global__ __launch_bounds__(256) void dwconv_kernel(const float* __restrict__ xn,
                                                     int in_off, int hw, int stride, int ohw,
                                                     const float* __restrict__ w,
                                                     const float* __restrict__ cb,
                                                     const float* __restrict__ bg,
                                                     const float* __restrict__ bb,
                                                     float* __restrict__ out,
                                                     int out_off, int out_ntok) {
    int idx = blockIdx.x * 256 + threadIdx.x;
    int total = Bt * ohw * ohw * Dm;
    if (idx >= total) return;
    int c = idx % Dm;
    int t = idx / Dm;
    int ox = t % ohw; t /= ohw;
    int oy = t % ohw;
    int b  = t / ohw;
    float acc = 0.f;
    const float* wc = w + c * 9;
    int iy0 = oy * stride - 1, ix0 = ox * stride - 1;
    #pragma unroll
    for (int dy = 0; dy < 3; dy++) {
        int iy = iy0 + dy;
        if ((unsigned)iy >= (unsigned)hw) continue;
        const float* rowp = xn + ((size_t)(b * Ntok + in_off + iy * hw)) * Dm + c;
        #pragma unroll
        for (int dx = 0; dx < 3; dx++) {
            int ix = ix0 + dx;
            if ((unsigned)ix < (unsigned)hw) acc += rowp[(size_t)ix * Dm] * wc[dy * 3 + dx];
        }
    }
    float y = acc + cb[c];
    y = y * (bg[c] * rsqrtf(1.0f + EPS_BN)) + bb[c];
    out[((size_t)(b * out_ntok + out_off + oy * ohw + ox)) * Dm + c] = y;
}

// ---------------- tf32 tensor-core GEMM ----------------
// C[M,N] = A[M,K] @ W[N,K]^T + bias ; epi: 0=none, 1=GELU, 2=residual add
// block tile 128x128x16, 8 warps of 64x32, mma.m16n8k8.tf32
__device__ __forceinline__ uint32_t f2tf32(float x) {
    uint32_t r;
    asm("cvt.rna.tf32.f32 %0, %1;" : "=r"(r) : "f"(x));
    return r;
}

constexpr int LDT = 20;   // smem row stride in floats (conflict-free for frag gather)

__global__ __launch_bounds__(256) void tgemm_kernel(const float* __restrict__ A,
                                                    const float* __restrict__ W,
                                                    const float* __restrict__ bias,
                                                    float* __restrict__ C,
                                                    int M, int N, int K, int epi,
                                                    const float* __restrict__ res) {
    __shared__ uint32_t As[128 * LDT];
    __shared__ uint32_t Bs[128 * LDT];

    const int bm = blockIdx.y * 128, bn = blockIdx.x * 128;
    const int tid = threadIdx.x;
    const int warp = tid >> 5, lane = tid & 31;
    const int wm = warp >> 2, wn = warp & 3;          // 2 x 4 warp grid
    const int g = lane >> 2, q = lane & 3;            // fragment lane coords

    float acc[4][4][4];
    #pragma unroll
    for (int i = 0; i < 4; i++)
        #pragma unroll
        for (int j = 0; j < 4; j++)
            #pragma unroll
            for (int c = 0; c < 4; c++) acc[i][j][c] = 0.f;

    const int lrow = tid >> 1;
    const int lcol = (tid & 1) * 8;
    const float* Ap = A + (size_t)(bm + lrow) * K + lcol;
    const float* Wp = W + (size_t)(bn + lrow) * K + lcol;

    for (int kt = 0; kt < K; kt += 16) {
        float4 a0 = *(const float4*)(Ap + kt);
        float4 a1 = *(const float4*)(Ap + kt + 4);
        float4 w0 = *(const float4*)(Wp + kt);
        float4 w1 = *(const float4*)(Wp + kt + 4);
        uint32_t* ad = As + lrow * LDT + lcol;
        ad[0] = f2tf32(a0.x); ad[1] = f2tf32(a0.y); ad[2] = f2tf32(a0.z); ad[3] = f2tf32(a0.w);
        ad[4] = f2tf32(a1.x); ad[5] = f2tf32(a1.y); ad[6] = f2tf32(a1.z); ad[7] = f2tf32(a1.w);
        uint32_t* bd = Bs + lrow * LDT + lcol;
        bd[0] = f2tf32(w0.x); bd[1] = f2tf32(w0.y); bd[2] = f2tf32(w0.z); bd[3] = f2tf32(w0.w);
        bd[4] = f2tf32(w1.x); bd[5] = f2tf32(w1.y); bd[6] = f2tf32(w1.z); bd[7] = f2tf32(w1.w);
        __syncthreads();

        #pragma unroll
        for (int ks = 0; ks < 2; ks++) {
            const int k0 = ks * 8;
            uint32_t af[4][4];
            #pragma unroll
            for (int mi = 0; mi < 4; mi++) {
                int row = wm * 64 + mi * 16 + g;
                af[mi][0] = As[(row    ) * LDT + k0 + q    ];
                af[mi][1] = As[(row + 8) * LDT + k0 + q    ];
                af[mi][2] = As[(row    ) * LDT + k0 + q + 4];
                af[mi][3] = As[(row + 8) * LDT + k0 + q + 4];
            }
            uint32_t bf[4][2];
            #pragma unroll
            for (int ni = 0; ni < 4; ni++) {
                int col = wn * 32 + ni * 8 + g;
                bf[ni][0] = Bs[col * LDT + k0 + q    ];
                bf[ni][1] = Bs[col * LDT + k0 + q + 4];
            }
            #pragma unroll
            for (int mi = 0; mi < 4; mi++)
                #pragma unroll
                for (int ni = 0; ni < 4; ni++) {
                    asm volatile(
                        "mma.sync.aligned.m16n8k8.row.col.f32.tf32.tf32.f32 "
                        "{%0,%1,%2,%3}, {%4,%5,%6,%7}, {%8,%9}, {%0,%1,%2,%3};\n"
                        : "+f"(acc[mi][ni][0]), "+f"(acc[mi][ni][1]),
                          "+f"(acc[mi][ni][2]), "+f"(acc[mi][ni][3])
                        : "r"(af[mi][0]), "r"(af[mi][1]), "r"(af[mi][2]), "r"(af[mi][3]),
                          "r"(bf[ni][0]), "r"(bf[ni][1]));
                }
        }
        __syncthreads();
    }

    // epilogue: each thread owns 2-float spans at (row,col) and (row+8,col)
    #pragma unroll
    for (int mi = 0; mi < 4; mi++) {
        #pragma unroll
        for (int ni = 0; ni < 4; ni++) {
            int row = bm + wm * 64 + mi * 16 + g;
            int col = bn + wn * 32 + ni * 8 + q * 2;
            float b0 = bias[col], b1 = bias[col + 1];
            #pragma unroll
            for (int half = 0; half < 2; half++) {
                int r = row + half * 8;
                float vx = acc[mi][ni][half * 2 + 0] + b0;
                float vy = acc[mi][ni][half * 2 + 1] + b1;
                if (epi == 1) {
                    vx = 0.5f * vx * (1.0f + erff(vx * 0.70710678118654752f));
                    vy = 0.5f * vy * (1.0f + erff(vy * 0.70710678118654752f));
                } else if (epi == 2) {
                    const float* rp = res + (size_t)r * N + col;
                    vx += rp[0];
                    vy += rp[1];
                }
                float2 o = make_float2(vx, vy);
                *(float2*)(C + (size_t)r * N + col) = o;
            }
        }
    }
}

// ---------------- attention scores ----------------
__global__ __launch_bounds__(128) void score_kernel(const float* __restrict__ q,
                                                    const float* __restrict__ k,
                                                    float* __restrict__ S,
                                                    int Mq, int Nk, int q_off, int k_off) {
    __shared__ __align__(16) float Qs[HD][32];
    __shared__ __align__(16) float Ks[HD][64];
    int bh = blockIdx.z;
    int b = bh >> 3, h = bh & 7;
    int m0 = blockIdx.y * 32, n0 = blockIdx.x * 64;
    int tid = threadIdx.x;

    for (int idx = tid; idx < HD * 32; idx += 128) {
        int d = idx >> 5, r = idx & 31;
        Qs[d][r] = q[((size_t)(b * Ntok + q_off + m0 + r)) * Dm + h * HD + d];
    }
    for (int idx = tid; idx < HD * 64; idx += 128) {
        int d = idx >> 6, r = idx & 63;
        Ks[d][r] = k[((size_t)(b * NKV + k_off + n0 + r)) * Dm + h * HD + d];
    }
    __syncthreads();

    int tn = tid & 15, tm = tid >> 4;
    float acc[4][4];
    #pragma unroll
    for (int i = 0; i < 4; i++)
        #pragma unroll
        for (int j = 0; j < 4; j++) acc[i][j] = 0.f;

    #pragma unroll
    for (int d = 0; d < HD; d++) {
        float4 av = ((const float4*)Qs[d])[tm];
        float4 bv = ((const float4*)Ks[d])[tn];
        float ar[4] = {av.x, av.y, av.z, av.w};
        float br[4] = {bv.x, bv.y, bv.z, bv.w};
        #pragma unroll
        for (int i = 0; i < 4; i++)
            #pragma unroll
            for (int j = 0; j < 4; j++) acc[i][j] += ar[i] * br[j];
    }

    float* Sp = S + (size_t)bh * Mq * Nk;
    #pragma unroll
    for (int i = 0; i < 4; i++) {
        float4 v;
        v.x = acc[i][0] * ATT_SCALE; v.y = acc[i][1] * ATT_SCALE;
        v.z = acc[i][2] * ATT_SCALE; v.w = acc[i][3] * ATT_SCALE;
        *(float4*)(Sp + (size_t)(m0 + tm * 4 + i) * Nk + n0 + tn * 4) = v;
    }
}

// ---------------- row softmax ----------------
__global__ __launch_bounds__(128) void softmax_kernel(float* __restrict__ S, int len) {
    float* row = S + (size_t)blockIdx.x * len;
    int t = threadIdx.x;
    __shared__ float red[4];
    __shared__ float s_bc;
    float m = -3.4e38f;
    for (int i = t; i < len; i += 128) m = fmaxf(m, row[i]);
    #pragma unroll
    for (int o = 16; o > 0; o >>= 1) m = fmaxf(m, __shfl_xor_sync(0xffffffffu, m, o));
    if ((t & 31) == 0) red[t >> 5] = m;
    __syncthreads();
    if (t == 0) s_bc = fmaxf(fmaxf(red[0], red[1]), fmaxf(red[2], red[3]));
    __syncthreads();
    float rowmax = s_bc;
    float sum = 0.f;
    for (int i = t; i < len; i += 128) {
        float e = __expf(row[i] - rowmax);
        row[i] = e;
        sum += e;
    }
    #pragma unroll
    for (int o = 16; o > 0; o >>= 1) sum += __shfl_xor_sync(0xffffffffu, sum, o);
    __syncthreads();
    if ((t & 31) == 0) red[t >> 5] = sum;
    __syncthreads();
    if (t == 0) s_bc = red[0] + red[1] + red[2] + red[3];
    __syncthreads();
    float inv = 1.0f / s_bc;
    for (int i = t; i < len; i += 128) row[i] *= inv;
}

// ---------------- PV + residual ----------------
__global__ __launch_bounds__(128) void pv_kernel(const float* __restrict__ P,
                                                 const float* __restrict__ v,
                                                 const float* __restrict__ x,
                                                 float* __restrict__ x1,
                                                 int Mq, int Nk, int q_off, int k_off) {
    __shared__ __align__(16) float Ps[128][65];
    __shared__ __align__(16) float Vs[64][52];
    int bh = blockIdx.y;
    int b = bh >> 3, h = bh & 7;
    int m0 = blockIdx.x * 128;
    int tid = threadIdx.x;
    float acc[48];
    #pragma unroll
    for (int j = 0; j < 48; j++) acc[j] = 0.f;

    const float* Prow = P + ((size_t)bh * Mq + m0) * Nk;
    for (int n0 = 0; n0 < Nk; n0 += 64) {
        for (int idx = tid; idx < 128 * 64; idx += 128) {
            int r = idx >> 6, c = idx & 63;
            Ps[r][c] = Prow[(size_t)r * Nk + n0 + c];
        }
        for (int idx = tid; idx < 64 * 48; idx += 128) {
            int r = idx / 48, c = idx % 48;
            Vs[r][c] = v[((size_t)(b * NKV + k_off + n0 + r)) * Dm + h * HD + c];
        }
        __syncthreads();
        #pragma unroll 4
        for (int n = 0; n < 64; n++) {
            float p = Ps[tid][n];
            const float4* vr = (const float4*)Vs[n];
            #pragma unroll
            for (int j = 0; j < 12; j++) {
                float4 vv = vr[j];
                acc[j * 4 + 0] += p * vv.x;
                acc[j * 4 + 1] += p * vv.y;
                acc[j * 4 + 2] += p * vv.z;
                acc[j * 4 + 3] += p * vv.w;
            }
        }
        __syncthreads();
    }
    size_t base = ((size_t)(b * Ntok + q_off + m0 + tid)) * Dm + h * HD;
    #pragma unroll
    for (int j = 0; j < 12; j++) {
        float4 xv = *(const float4*)(x + base + j * 4);
        float4 o;
        o.x = xv.x + acc[j * 4 + 0];
        o.y = xv.y + acc[j * 4 + 1];
        o.z = xv.z + acc[j * 4 + 2];
        o.w = xv.w + acc[j * 4 + 3];
        *(float4*)(x1 + base + j * 4) = o;
    }
}

// ---------------- launch ----------------
extern "C" void kernel_launch(void* const* d_in, const int* in_sizes, int n_in,
                              void* d_out, int out_size) {
    const float* x      = (const float*)d_in[0];
    const float* ln1_g  = (const float*)d_in[1];
    const float* ln1_b  = (const float*)d_in[2];
    const float* dwq_w  = (const float*)d_in[3];
    const float* dwq_b  = (const float*)d_in[4];
    const float* bnq_g  = (const float*)d_in[5];
    const float* bnq_b  = (const float*)d_in[6];
    const float* dwk_w  = (const float*)d_in[7];
    const float* dwk_b  = (const float*)d_in[8];
    const float* bnk_g  = (const float*)d_in[9];
    const float* bnk_b  = (const float*)d_in[10];
    const float* dwv_w  = (const float*)d_in[11];
    const float* dwv_b  = (const float*)d_in[12];
    const float* bnv_g  = (const float*)d_in[13];
    const float* bnv_b  = (const float*)d_in[14];
    const float* pq_w   = (const float*)d_in[15];
    const float* pq_b   = (const float*)d_in[16];
    const float* pk_w   = (const float*)d_in[17];
    const float* pk_b   = (const float*)d_in[18];
    const float* pv_w   = (const float*)d_in[19];
    const float* pv_b   = (const float*)d_in[20];
    const float* ln2_g  = (const float*)d_in[21];
    const float* ln2_b  = (const float*)d_in[22];
    const float* ff1_w  = (const float*)d_in[23];
    const float* ff1_b  = (const float*)d_in[24];
    const float* ff2_w  = (const float*)d_in[25];
    const float* ff2_b  = (const float*)d_in[26];
    float* out = (float*)d_out;

    float *xn, *qact, *kact, *vact, *q, *k, *v, *Ss, *St, *x1, *h, *hid;
    cudaGetSymbolAddress((void**)&xn,   g_xn);
    cudaGetSymbolAddress((void**)&qact, g_qact);
    cudaGetSymbolAddress((void**)&kact, g_kact);
    cudaGetSymbolAddress((void**)&vact, g_vact);
    cudaGetSymbolAddress((void**)&q,    g_q);
    cudaGetSymbolAddress((void**)&k,    g_k);
    cudaGetSymbolAddress((void**)&v,    g_v);
    cudaGetSymbolAddress((void**)&Ss,   g_Ss);
    cudaGetSymbolAddress((void**)&St,   g_St);
    cudaGetSymbolAddress((void**)&x1,   g_x1);
    cudaGetSymbolAddress((void**)&h,    g_h);
    cudaGetSymbolAddress((void**)&hid,  g_hid);

    // 1) LN1
    ln_kernel<<<Bt * Ntok, 128>>>(x, ln1_g, ln1_b, xn);

    // 2) depthwise convs + BN
    {
        int tot;
        tot = Bt * 32 * 32 * Dm;
        dwconv_kernel<<<(tot + 255) / 256, 256>>>(xn, 0,  32, 1, 32, dwq_w, dwq_b, bnq_g, bnq_b, qact, 0,  Ntok);
        tot = Bt * 16 * 16 * Dm;
        dwconv_kernel<<<(tot + 255) / 256, 256>>>(xn, NS, 16, 1, 16, dwq_w, dwq_b, bnq_g, bnq_b, qact, NS, Ntok);
        tot = Bt * 16 * 16 * Dm;
        dwconv_kernel<<<(tot + 255) / 256, 256>>>(xn, 0,  32, 2, 16, dwk_w, dwk_b, bnk_g, bnk_b, kact, 0,  NKV);
        tot = Bt * 8 * 8 * Dm;
        dwconv_kernel<<<(tot + 255) / 256, 256>>>(xn, NS, 16, 2, 8,  dwk_w, dwk_b, bnk_g, bnk_b, kact, SKV, NKV);
        tot = Bt * 16 * 16 * Dm;
        dwconv_kernel<<<(tot + 255) / 256, 256>>>(xn, 0,  32, 2, 16, dwv_w, dwv_b, bnv_g, bnv_b, vact, 0,  NKV);
        tot = Bt * 8 * 8 * Dm;
        dwconv_kernel<<<(tot + 255) / 256, 256>>>(xn, NS, 16, 2, 8,  dwv_w, dwv_b, bnv_g, bnv_b, vact, SKV, NKV);
    }

    // 3) q/k/v projections (tensor core tf32)
    {
        dim3 gq(Dm / 128, (Bt * Ntok) / 128);
        tgemm_kernel<<<gq, 256>>>(qact, pq_w, pq_b, q, Bt * Ntok, Dm, Dm, 0, nullptr);
        dim3 gk(Dm / 128, (Bt * NKV) / 128);
        tgemm_kernel<<<gk, 256>>>(kact, pk_w, pk_b, k, Bt * NKV, Dm, Dm, 0, nullptr);
        tgemm_kernel<<<gk, 256>>>(vact, pv_w, pv_b, v, Bt * NKV, Dm, Dm, 0, nullptr);
    }

    // 4) attention
    score_kernel<<<dim3(NKV / 64, NS / 32, Bt * Hh), 128>>>(q, k, Ss, NS, NKV, 0, 0);
    score_kernel<<<dim3(TKV / 64, NT / 32, Bt * Hh), 128>>>(q, k, St, NT, TKV, NS, SKV);
    softmax_kernel<<<Bt * Hh * NS, 128>>>(Ss, NKV);
    softmax_kernel<<<Bt * Hh * NT, 128>>>(St, TKV);
    pv_kernel<<<dim3(NS / 128, Bt * Hh), 128>>>(Ss, v, x, x1, NS, NKV, 0, 0);
    pv_kernel<<<dim3(NT / 128, Bt * Hh), 128>>>(St, v, x, x1, NT, TKV, NS, SKV);

    // 5) LN2 + FFN (tensor core tf32, GELU / residual fused)
    ln_kernel<<<Bt * Ntok, 128>>>(x1, ln2_g, ln2_b, h);
    {
        dim3 g1(FF / 128, (Bt * Ntok) / 128);
        tgemm_kernel<<<g1, 256>>>(h, ff1_w, ff1_b, hid, Bt * Ntok, FF, Dm, 1, nullptr);
        dim3 g2(Dm / 128, (Bt * Ntok) / 128);
        tgemm_kernel<<<g2, 256>>>(hid, ff2_w, ff2_b, out, Bt * Ntok, Dm, FF, 2, x1);
    }
}